// round 1
// baseline (speedup 1.0000x reference)
#include <cuda_runtime.h>
#include <cuda_bf16.h>
#include <cstdint>

// Problem constants (fixed shapes)
#define BB 1024
#define SS 512
#define TT 48

__device__ float g_scratch[BB];

__device__ __forceinline__ unsigned long long pack2f(float a, float b) {
    unsigned long long r;
    asm("mov.b64 %0, {%1, %2};" : "=l"(r) : "f"(a), "f"(b));
    return r;
}
__device__ __forceinline__ void unpack2f(unsigned long long v, float& lo, float& hi) {
    asm("mov.b64 {%0, %1}, %2;" : "=f"(lo), "=f"(hi) : "l"(v));
}
__device__ __forceinline__ void fma2(unsigned long long& acc, unsigned long long a, unsigned long long b) {
    asm("fma.rn.f32x2 %0, %1, %2, %0;" : "+l"(acc) : "l"(a), "l"(b));
}

__device__ __forceinline__ float warp_max(float v) {
    #pragma unroll
    for (int o = 16; o; o >>= 1) v = fmaxf(v, __shfl_xor_sync(0xFFFFFFFFu, v, o));
    return v;
}
__device__ __forceinline__ float warp_sum(float v) {
    #pragma unroll
    for (int o = 16; o; o >>= 1) v += __shfl_xor_sync(0xFFFFFFFFu, v, o);
    return v;
}

#define NEG_INF __int_as_float(0xff800000)

// One warp per batch. Lane l owns output tags j=l and j=l+32 (latter only lanes 0..15).
// exp(transitions) columns held in registers, packed as f32x2 pairs along the i (row) axis.
// Per step: q[j] = sum_i p[i] * E[i][j] via fma.rn.f32x2 with packed partial accumulators;
// p broadcast through shared memory (LDS.128-equivalent v2.u64 broadcasts, conflict-free).
extern "C" __global__ void __launch_bounds__(128)
crf_fwd_kernel(const float* __restrict__ em,      // [B,S,T]
               const int*   __restrict__ tags,    // [B,S]
               const float* __restrict__ mask,    // [B,S]
               const float* __restrict__ trans,   // [T,T]
               const float* __restrict__ startt,  // [T]
               const float* __restrict__ endt)    // [T]
{
    const int w    = threadIdx.x >> 5;            // warp in block (0..3)
    const int lane = threadIdx.x & 31;
    const int b    = blockIdx.x * 4 + w;          // batch
    if (b >= BB) return;

    __shared__ __align__(16) float p_buf[4][64];

    const int c0 = lane;
    const int c1 = (lane < 16) ? (lane + 32) : lane;   // clamped second column
    const bool has2 = (lane < 16);

    // ---- sequence length from mask (monotone prefix of 1s) ----
    float msum = 0.f;
    #pragma unroll
    for (int k = 0; k < SS / 32; k++) msum += mask[b * SS + k * 32 + lane];
    int len = __float2int_rn(warp_sum(msum));

    // ---- gold path score ----
    float g = 0.f;
    const int tagbase = b * SS;
    const long embase = (long)b * SS * TT;
    #pragma unroll 4
    for (int it = 0; it < SS / 32; it++) {
        int t = lane + it * 32;
        if (t < len) {
            int tg = tags[tagbase + t];
            if (t == 0) {
                g += __ldg(&startt[tg]) + __ldg(&em[embase + tg]);
            } else {
                int tp = tags[tagbase + t - 1];
                g += __ldg(&trans[tg * TT + tp]) + __ldg(&em[embase + (long)t * TT + tg]);
            }
            if (t == len - 1) g += __ldg(&endt[tg]);
        }
    }
    float gold = warp_sum(g);

    // ---- load exp(transitions) columns into registers, packed along rows ----
    unsigned long long e0p[TT / 2], e1p[TT / 2];
    #pragma unroll
    for (int k = 0; k < TT / 2; k++) {
        float a0 = __expf(__ldg(&trans[(2 * k)     * TT + c0]));
        float a1 = __expf(__ldg(&trans[(2 * k + 1) * TT + c0]));
        e0p[k] = pack2f(a0, a1);
        float bb0 = __expf(__ldg(&trans[(2 * k)     * TT + c1]));
        float bb1 = __expf(__ldg(&trans[(2 * k + 1) * TT + c1]));
        e1p[k] = pack2f(bb0, bb1);
    }

    // ---- init scores at t = 0 ----
    float s0 = __ldg(&startt[c0]) + em[embase + c0];
    float s1 = has2 ? (__ldg(&startt[c1]) + em[embase + c1]) : NEG_INF;

    // ---- emission prefetch (depth 2) ----
    float a0 = 0.f, a1 = 0.f, f0 = 0.f, f1 = 0.f;
    if (len > 1) { a0 = em[embase + 1L * TT + c0]; a1 = em[embase + 1L * TT + c1]; }
    if (len > 2) { f0 = em[embase + 2L * TT + c0]; f1 = em[embase + 2L * TT + c1]; }

    const unsigned paddr = (unsigned)__cvta_generic_to_shared(&p_buf[w][0]);

    // ---- forward recurrence ----
    for (int t = 1; t < len; t++) {
        float cur0 = a0, cur1 = a1;
        a0 = f0; a1 = f1;
        int tn = t + 2;
        if (tn < len) {
            f0 = em[embase + (long)tn * TT + c0];
            f1 = em[embase + (long)tn * TT + c1];
        }

        // m = max_i score[i]
        float m = warp_max(fmaxf(s0, s1));   // s1 == -inf on lanes >= 16

        // p = exp(score - m); exp(-inf) = 0 so hi-lane second slot is harmless
        float p0 = __expf(s0 - m);
        float p1 = __expf(s1 - m);

        __syncwarp();
        p_buf[w][lane] = p0;
        p_buf[w][lane + 32] = p1;            // lanes>=16 write slots 48..63 (padding)
        __syncwarp();

        // q[j] = sum_i p[i] * E[i][j], packed partial sums along i
        unsigned long long q0p = 0ull, q1p = 0ull;
        #pragma unroll
        for (int c = 0; c < 12; c++) {
            unsigned long long p01, p23;
            asm("ld.shared.v2.u64 {%0, %1}, [%2];"
                : "=l"(p01), "=l"(p23) : "r"(paddr + c * 16));
            fma2(q0p, p01, e0p[2 * c]);
            fma2(q1p, p01, e1p[2 * c]);
            fma2(q0p, p23, e0p[2 * c + 1]);
            fma2(q1p, p23, e1p[2 * c + 1]);
        }
        float q0lo, q0hi, q1lo, q1hi;
        unpack2f(q0p, q0lo, q0hi);
        unpack2f(q1p, q1lo, q1hi);
        float q0 = q0lo + q0hi;
        float q1 = q1lo + q1hi;

        s0 = m + __logf(q0) + cur0;
        float ns1 = m + __logf(q1) + cur1;
        s1 = has2 ? ns1 : NEG_INF;
    }

    // ---- final logsumexp(score + end_transitions) ----
    float v0 = s0 + __ldg(&endt[c0]);
    float v1 = has2 ? (s1 + __ldg(&endt[c1])) : NEG_INF;
    float mm = warp_max(fmaxf(v0, v1));
    float sm = warp_sum(__expf(v0 - mm) + __expf(v1 - mm));
    float fwd = mm + __logf(sm);

    if (lane == 0) g_scratch[b] = fwd - gold;
}

extern "C" __global__ void crf_reduce_kernel(float* __restrict__ out) {
    __shared__ double sh[256];
    double s = 0.0;
    for (int i = threadIdx.x; i < BB; i += 256) s += (double)g_scratch[i];
    sh[threadIdx.x] = s;
    __syncthreads();
    for (int o = 128; o; o >>= 1) {
        if (threadIdx.x < o) sh[threadIdx.x] += sh[threadIdx.x + o];
        __syncthreads();
    }
    if (threadIdx.x == 0) out[0] = (float)(sh[0] / (double)BB);
}

extern "C" void kernel_launch(void* const* d_in, const int* in_sizes, int n_in,
                              void* d_out, int out_size) {
    const float* em     = (const float*)d_in[0];
    const int*   tags   = (const int*)d_in[1];
    const float* mask   = (const float*)d_in[2];
    const float* trans  = (const float*)d_in[3];
    const float* startt = (const float*)d_in[4];
    const float* endt   = (const float*)d_in[5];
    float* out = (float*)d_out;

    crf_fwd_kernel<<<BB / 4, 128>>>(em, tags, mask, trans, startt, endt);
    crf_reduce_kernel<<<1, 256>>>(out);
}

// round 2
// speedup vs baseline: 1.1542x; 1.1542x over previous
#include <cuda_runtime.h>
#include <cuda_bf16.h>
#include <cstdint>

#define BB 1024
#define SS 512
#define TT 48
#define FULL 0xFFFFFFFFu

typedef unsigned long long ull;

__device__ double g_scratch[BB];
__device__ unsigned int g_count = 0;

__device__ __forceinline__ ull pack2f(float a, float b) {
    ull r;
    asm("mov.b64 %0, {%1, %2};" : "=l"(r) : "f"(a), "f"(b));
    return r;
}
__device__ __forceinline__ void unpack2f(ull v, float& lo, float& hi) {
    asm("mov.b64 {%0, %1}, %2;" : "=f"(lo), "=f"(hi) : "l"(v));
}
__device__ __forceinline__ void fma2(ull& acc, ull a, ull b) {
    asm("fma.rn.f32x2 %0, %1, %2, %0;" : "+l"(acc) : "l"(a), "l"(b));
}
__device__ __forceinline__ float warp_sum_f(float v) {
    #pragma unroll
    for (int o = 16; o; o >>= 1) v += __shfl_xor_sync(FULL, v, o);
    return v;
}

// One warp per batch. Lane l owns output tags j=l and (l<16) j=l+32.
// Product-domain forward recurrence: p'_j = (sum_i p_i * E_ij) * exp(em_j),
// E = exp(transitions) held in registers packed f32x2 along i.
// Rescale by lane-0 broadcast every 4 steps; shift accumulated in double M.
extern "C" __global__ void __launch_bounds__(128, 2)
crf_kernel(const float* __restrict__ em,      // [B,S,T]
           const int*   __restrict__ tags,    // [B,S]
           const float* __restrict__ mask,    // [B,S]
           const float* __restrict__ trans,   // [T,T]
           const float* __restrict__ startt,  // [T]
           const float* __restrict__ endt,    // [T]
           float* __restrict__ out)
{
    const int w    = threadIdx.x >> 5;
    const int lane = threadIdx.x & 31;
    const int b    = blockIdx.x * 4 + w;

    __shared__ __align__(16) float p_buf[4][2][64];

    const int  c0   = lane;
    const int  c1   = (lane < 16) ? (lane + 32) : lane;
    const bool has2 = (lane < 16);

    // ---- sequence length from mask (monotone prefix of ones) ----
    float msum = 0.f;
    #pragma unroll
    for (int k = 0; k < SS / 32; k++) msum += mask[b * SS + k * 32 + lane];
    const int len = __float2int_rn(warp_sum_f(msum));

    // ---- gold path score ----
    float g = 0.f;
    const int  tagbase = b * SS;
    const long embase  = (long)b * SS * TT;
    #pragma unroll 4
    for (int it = 0; it < SS / 32; it++) {
        int t = lane + it * 32;
        if (t < len) {
            int tg = tags[tagbase + t];
            if (t == 0) {
                g += __ldg(&startt[tg]) + __ldg(&em[embase + tg]);
            } else {
                int tp = tags[tagbase + t - 1];
                g += __ldg(&trans[tg * TT + tp]) + __ldg(&em[embase + (long)t * TT + tg]);
            }
            if (t == len - 1) g += __ldg(&endt[tg]);
        }
    }
    const float gold = warp_sum_f(g);

    // ---- E = exp(transitions), columns c0/c1, packed along row pairs ----
    ull e0p[TT / 2], e1p[TT / 2];
    #pragma unroll
    for (int k = 0; k < TT / 2; k++) {
        float a0 = __expf(__ldg(&trans[(2 * k)     * TT + c0]));
        float a1 = __expf(__ldg(&trans[(2 * k + 1) * TT + c0]));
        e0p[k] = pack2f(a0, a1);
        float b0 = __expf(__ldg(&trans[(2 * k)     * TT + c1]));
        float b1 = __expf(__ldg(&trans[(2 * k + 1) * TT + c1]));
        e1p[k] = pack2f(b0, b1);
    }

    const float* emp = em + embase;

    // ---- init at t = 0 (product domain, shifted by lane-0 score) ----
    float s0  = __ldg(&startt[c0]) + emp[c0];
    float s1v = __ldg(&startt[c1]) + emp[c1];
    float sref = __shfl_sync(FULL, s0, 0);
    double M = (double)sref;
    float p0 = __expf(s0 - sref);
    float p1 = has2 ? __expf(s1v - sref) : 0.f;

    // ---- emission prefetch (depth 2, raw values; exp'd one step before use) ----
    float nxt0 = 0.f, nxt1 = 0.f, nn0 = 0.f, nn1 = 0.f;
    if (len > 1) { nxt0 = emp[TT + c0];     nxt1 = emp[TT + c1]; }
    if (len > 2) { nn0  = emp[2 * TT + c0]; nn1  = emp[2 * TT + c1]; }

    const unsigned pbase = (unsigned)__cvta_generic_to_shared(&p_buf[w][0][0]);

    // ---- forward recurrence ----
    for (int t = 1; t < len; t++) {
        float ce0 = __expf(nxt0);
        float ce1 = __expf(nxt1);
        nxt0 = nn0; nxt1 = nn1;
        if (t + 2 < len) {
            nn0 = emp[(long)(t + 2) * TT + c0];
            nn1 = emp[(long)(t + 2) * TT + c1];
        }

        const unsigned pa = pbase + (unsigned)((t & 1) * 256);
        asm volatile("st.shared.f32 [%0], %1;" :: "r"(pa + lane * 4),        "f"(p0));
        asm volatile("st.shared.f32 [%0], %1;" :: "r"(pa + (lane + 32) * 4), "f"(p1));
        __syncwarp();

        // q_j = sum_i p_i * E_ij, 4 packed accumulators (chain depth 12)
        ull q0a = 0ull, q0b = 0ull, q1a = 0ull, q1b = 0ull;
        #pragma unroll
        for (int c = 0; c < 6; c++) {
            ull pA, pB, pC, pD;
            asm("ld.shared.v2.u64 {%0, %1}, [%2];"
                : "=l"(pA), "=l"(pB) : "r"(pa + c * 32));
            asm("ld.shared.v2.u64 {%0, %1}, [%2];"
                : "=l"(pC), "=l"(pD) : "r"(pa + c * 32 + 16));
            fma2(q0a, pA, e0p[4 * c    ]);  fma2(q1a, pA, e1p[4 * c    ]);
            fma2(q0b, pB, e0p[4 * c + 1]);  fma2(q1b, pB, e1p[4 * c + 1]);
            fma2(q0a, pC, e0p[4 * c + 2]);  fma2(q1a, pC, e1p[4 * c + 2]);
            fma2(q0b, pD, e0p[4 * c + 3]);  fma2(q1b, pD, e1p[4 * c + 3]);
        }
        float x0, x1, y0, y1;
        unpack2f(q0a, x0, x1); unpack2f(q0b, y0, y1);
        const float q0 = (x0 + y0) + (x1 + y1);
        unpack2f(q1a, x0, x1); unpack2f(q1b, y0, y1);
        const float q1 = (x0 + y0) + (x1 + y1);

        p0 = q0 * ce0;
        p1 = has2 ? (q1 * ce1) : 0.f;

        if ((t & 3) == 0) {
            float pref = __shfl_sync(FULL, p0, 0);
            float inv  = __fdividef(1.f, pref);
            p0 *= inv;
            p1 *= inv;
            M += (double)__logf(pref);
        }
    }

    // ---- final: fwd = M + log(sum_j p_j * exp(end_j)) ----
    float v = p0 * __expf(__ldg(&endt[c0]));
    if (has2) v += p1 * __expf(__ldg(&endt[c1]));
    const float ssum = warp_sum_f(v);
    if (lane == 0)
        g_scratch[b] = M + (double)__logf(ssum) - (double)gold;

    // ---- fused mean reduction: last block to finish reduces ----
    __syncthreads();
    __shared__ bool is_last;
    if (threadIdx.x == 0) {
        __threadfence();
        unsigned r = atomicAdd(&g_count, 1u);
        is_last = (r == gridDim.x - 1);
    }
    __syncthreads();
    if (is_last) {
        __threadfence();
        double s = 0.0;
        for (int i = threadIdx.x; i < BB; i += 128) s += g_scratch[i];
        __shared__ double sh[128];
        sh[threadIdx.x] = s;
        __syncthreads();
        #pragma unroll
        for (int o = 64; o; o >>= 1) {
            if (threadIdx.x < o) sh[threadIdx.x] += sh[threadIdx.x + o];
            __syncthreads();
        }
        if (threadIdx.x == 0) {
            out[0] = (float)(sh[0] / (double)BB);
            g_count = 0;   // reset for next graph replay
        }
    }
}

extern "C" void kernel_launch(void* const* d_in, const int* in_sizes, int n_in,
                              void* d_out, int out_size) {
    const float* em     = (const float*)d_in[0];
    const int*   tags   = (const int*)d_in[1];
    const float* mask   = (const float*)d_in[2];
    const float* trans  = (const float*)d_in[3];
    const float* startt = (const float*)d_in[4];
    const float* endt   = (const float*)d_in[5];
    float* out = (float*)d_out;

    crf_kernel<<<BB / 4, 128>>>(em, tags, mask, trans, startt, endt, out);
}